// round 11
// baseline (speedup 1.0000x reference)
#include <cuda_runtime.h>
#include <cuda_bf16.h>

#define BB 16
#define NN 4096
#define DD 512
#define KK 128
#define REGC 1e-6f

typedef unsigned long long ull;

__device__ __forceinline__ ull pack2(float x, float y) {
    ull r; asm("mov.b64 %0, {%1, %2};" : "=l"(r) : "f"(x), "f"(y)); return r;
}
__device__ __forceinline__ void unpack2(ull v, float& lo, float& hi) {
    asm("mov.b64 {%0, %1}, %2;" : "=f"(lo), "=f"(hi) : "l"(v));
}
__device__ __forceinline__ void ffma2(ull& d, ull a, ull b) {
    asm("fma.rn.f32x2 %0, %1, %2, %0;" : "+l"(d) : "l"(a), "l"(b));
}
__device__ __forceinline__ unsigned smem_u32(const void* p) {
    unsigned a;
    asm("{ .reg .u64 t; cvta.to.shared.u64 t, %1; cvt.u32.u64 %0, t; }" : "=r"(a) : "l"(p));
    return a;
}
__device__ __forceinline__ void ldm4(unsigned* r, unsigned addr) {
    asm volatile("ldmatrix.sync.aligned.m8n8.x4.shared.b16 {%0,%1,%2,%3}, [%4];"
                 : "=r"(r[0]), "=r"(r[1]), "=r"(r[2]), "=r"(r[3]) : "r"(addr));
}
__device__ __forceinline__ void mma_bf16(float* d, const unsigned* a, const unsigned* b) {
    asm volatile(
        "mma.sync.aligned.m16n8k16.row.col.f32.bf16.bf16.f32 "
        "{%0,%1,%2,%3}, {%4,%5,%6,%7}, {%8,%9}, {%0,%1,%2,%3};"
        : "+f"(d[0]), "+f"(d[1]), "+f"(d[2]), "+f"(d[3])
        : "r"(a[0]), "r"(a[1]), "r"(a[2]), "r"(a[3]), "r"(b[0]), "r"(b[1]));
}
__device__ __forceinline__ float lds_f32(unsigned a) {
    float v; asm volatile("ld.shared.f32 %0, [%1];" : "=f"(v) : "r"(a)); return v;
}
__device__ __forceinline__ void sts128(unsigned a, unsigned r0, unsigned r1,
                                       unsigned r2, unsigned r3) {
    asm volatile("st.shared.v4.b32 [%0], {%1,%2,%3,%4};"
                 :: "r"(a), "r"(r0), "r"(r1), "r"(r2), "r"(r3) : "memory");
}
#define SWZ(o) ((o) ^ (((o) >> 3) & 0x70))

// Scratch
__device__ float g_Sinv[2 * BB * KK * KK];
__device__ float g_R[BB * KK * KK];
__device__ float g_RT[BB * KK * KK];
__device__ float g_D[2 * BB * KK * KK];
__device__ float g_X0[2 * BB * KK * KK];
__device__ float g_X1[2 * BB * KK * KK];
__device__ __nv_bfloat16 g_Ehi[2 * BB * KK * NN];
__device__ __nv_bfloat16 g_Elo[2 * BB * KK * NN];
__device__ __nv_bfloat16 g_ABhi[2 * BB * KK * DD];
__device__ __nv_bfloat16 g_ABlo[2 * BB * KK * DD];

__device__ __forceinline__ void split1(float x, unsigned short& h, unsigned short& l) {
    __nv_bfloat16 hb = __float2bfloat16_rn(x);
    float r = x - __bfloat162float(hb);
    __nv_bfloat16 lb = __float2bfloat16_rn(r);
    h = __bfloat16_as_ushort(hb);
    l = __bfloat16_as_ushort(lb);
}

// ---------------------------------------------------------------------------
// split_E: evecs fp32 [b][128][4096] -> g_Ehi/g_Elo bf16
// ---------------------------------------------------------------------------
__global__ void split_E(const float* __restrict__ ex, const float* __restrict__ ey) {
    int w = blockIdx.y;
    const float* E = w ? ey : ex;
    size_t i4 = (size_t)blockIdx.x * 256 + threadIdx.x;
    float4 t = *((const float4*)E + i4);
    unsigned short h0, h1, h2, h3, l0, l1, l2, l3;
    split1(t.x, h0, l0); split1(t.y, h1, l1); split1(t.z, h2, l2); split1(t.w, h3, l3);
    ull hp = (ull)h0 | ((ull)h1 << 16) | ((ull)h2 << 32) | ((ull)h3 << 48);
    ull lp = (ull)l0 | ((ull)l1 << 16) | ((ull)l2 << 32) | ((ull)l3 << 48);
    size_t o = (size_t)w * (BB * KK * NN) + i4 * 4;
    *(ull*)(g_Ehi + o) = hp;
    *(ull*)(g_Elo + o) = lp;
}

// ---------------------------------------------------------------------------
// mma_proj (unchanged from R10)
// ---------------------------------------------------------------------------
#define CONV_BH 0
#define CONV_BL 16384
#define STAGE0 32768
#define STAGE_SZ 65536
#define MMA_SMEM (1024 + STAGE0 + 3 * STAGE_SZ)

__global__ void __launch_bounds__(256, 1) mma_proj(const float* __restrict__ fx,
                                                   const float* __restrict__ fy) {
    extern __shared__ char smraw[];
    unsigned base = (smem_u32(smraw) + 1023) & ~1023u;
    int tid = threadIdx.x, wid = tid >> 5, lane = tid & 31;

    int p = blockIdx.y; int w = p >> 4, b = p & 15;
    int n0 = blockIdx.x * 128;
    const __nv_bfloat16* Eh = g_Ehi + (size_t)p * KK * NN;
    const __nv_bfloat16* El = g_Elo + (size_t)p * KK * NN;
    const float* Ff = (w ? fy : fx) + (size_t)b * NN * DD + n0;
    size_t cbase = (size_t)p * KK * DD + n0;

    int wm = (wid & 1) * 64, wn = (wid >> 1) * 32;

    float acc[4][4][4];
#pragma unroll
    for (int mt = 0; mt < 4; mt++)
#pragma unroll
        for (int nt = 0; nt < 4; nt++)
#pragma unroll
            for (int i = 0; i < 4; i++) acc[mt][nt][i] = 0.0f;

    unsigned msk = (unsigned)((lane & 7) << 4);
    unsigned a_c0 = (unsigned)((lane >> 4) * 16);
    unsigned b_c0 = (unsigned)(((lane >> 3) & 1) * 16);
    unsigned a_row[4], b_row[2];
#pragma unroll
    for (int mt = 0; mt < 4; mt++)
        a_row[mt] = (unsigned)((wm + mt * 16 + (lane & 15)) * 128);
#pragma unroll
    for (int np = 0; np < 2; np++)
        b_row[np] = (unsigned)((wn + np * 16 + ((lane >> 4) << 3) + (lane & 7)) * 128);

    int cd = tid & 127, ckg = tid >> 7;

    auto issue = [&](int c) {
        unsigned stage = base + STAGE0 + (unsigned)(c % 3) * STAGE_SZ;
        int k0 = c * 64;
#pragma unroll
        for (int u = 0; u < 8; u++) {
            int tile = u >> 2;
            int v = tid + (u & 3) * 256;
            int r = v >> 3, s = v & 7;
            unsigned sa = stage + tile * 16384 + SWZ((unsigned)(r * 128 + s * 16));
            const __nv_bfloat16* g = (tile ? El : Eh) + (size_t)r * NN + k0 + s * 8;
            asm volatile("cp.async.cg.shared.global [%0], [%1], 16;"
                         :: "r"(sa), "l"(g) : "memory");
        }
#pragma unroll
        for (int u = 0; u < 8; u++) {
            int v = tid + u * 256;
            int r = v >> 5, s = v & 31;
            unsigned sa = stage + 32768 + (unsigned)(r * 512 + s * 16);
            const float* g = Ff + (size_t)(k0 + r) * DD + s * 4;
            asm volatile("cp.async.cg.shared.global [%0], [%1], 16;"
                         :: "r"(sa), "l"(g) : "memory");
        }
        asm volatile("cp.async.commit_group;" ::: "memory");
    };

    issue(0);
    issue(1);
    for (int c = 0; c < 64; c++) {
        if (c < 63)
            asm volatile("cp.async.wait_group 1;" ::: "memory");
        else
            asm volatile("cp.async.wait_group 0;" ::: "memory");
        __syncthreads();

        unsigned stage = base + STAGE0 + (unsigned)(c % 3) * STAGE_SZ;
        {
            unsigned fpb = stage + 32768;
#pragma unroll
            for (int kq = 0; kq < 4; kq++) {
                int kstart = ckg * 8 + kq * 16;
                unsigned hw[4], lw[4];
#pragma unroll
                for (int w2 = 0; w2 < 4; w2++) {
                    float x0 = lds_f32(fpb + (unsigned)(((kstart + 2 * w2) * 128 + cd) * 4));
                    float x1 = lds_f32(fpb + (unsigned)(((kstart + 2 * w2 + 1) * 128 + cd) * 4));
                    unsigned short h0, l0, h1, l1;
                    split1(x0, h0, l0); split1(x1, h1, l1);
                    hw[w2] = (unsigned)h0 | ((unsigned)h1 << 16);
                    lw[w2] = (unsigned)l0 | ((unsigned)l1 << 16);
                }
                unsigned off = SWZ((unsigned)(cd * 128 + kstart * 2));
                sts128(base + CONV_BH + off, hw[0], hw[1], hw[2], hw[3]);
                sts128(base + CONV_BL + off, lw[0], lw[1], lw[2], lw[3]);
            }
        }
        __syncthreads();
        if (c + 2 < 64) issue(c + 2);

        unsigned sAh = stage, sAl = stage + 16384;
        unsigned sBh = base + CONV_BH, sBl = base + CONV_BL;
#pragma unroll
        for (int kk = 0; kk < 4; kk++) {
            unsigned ca = (a_c0 + (unsigned)(kk * 32)) ^ msk;
            unsigned cb = (b_c0 + (unsigned)(kk * 32)) ^ msk;
            unsigned ah[4][4], al[4][4], bh[2][4], bl[2][4];
#pragma unroll
            for (int mt = 0; mt < 4; mt++) {
                ldm4(ah[mt], sAh + a_row[mt] + ca);
                ldm4(al[mt], sAl + a_row[mt] + ca);
            }
#pragma unroll
            for (int np = 0; np < 2; np++) {
                ldm4(bh[np], sBh + b_row[np] + cb);
                ldm4(bl[np], sBl + b_row[np] + cb);
            }
#pragma unroll
            for (int mt = 0; mt < 4; mt++)
#pragma unroll
                for (int nt = 0; nt < 4; nt++)
                    mma_bf16(acc[mt][nt], ah[mt], &bh[nt >> 1][(nt & 1) * 2]);
#pragma unroll
            for (int mt = 0; mt < 4; mt++)
#pragma unroll
                for (int nt = 0; nt < 4; nt++)
                    mma_bf16(acc[mt][nt], ah[mt], &bl[nt >> 1][(nt & 1) * 2]);
#pragma unroll
            for (int mt = 0; mt < 4; mt++)
#pragma unroll
                for (int nt = 0; nt < 4; nt++)
                    mma_bf16(acc[mt][nt], al[mt], &bh[nt >> 1][(nt & 1) * 2]);
        }
    }

#pragma unroll
    for (int mt = 0; mt < 4; mt++) {
#pragma unroll
        for (int nt = 0; nt < 4; nt++) {
            int r0 = wm + mt * 16 + (lane >> 2);
            int c0 = wn + nt * 8 + (lane & 3) * 2;
            unsigned short h0, l0, h1, l1, h2, l2, h3, l3;
            split1(acc[mt][nt][0], h0, l0);
            split1(acc[mt][nt][1], h1, l1);
            split1(acc[mt][nt][2], h2, l2);
            split1(acc[mt][nt][3], h3, l3);
            size_t o01 = cbase + (size_t)r0 * DD + c0;
            size_t o23 = cbase + (size_t)(r0 + 8) * DD + c0;
            *(unsigned*)(g_ABhi + o01) = (unsigned)h0 | ((unsigned)h1 << 16);
            *(unsigned*)(g_ABlo + o01) = (unsigned)l0 | ((unsigned)l1 << 16);
            *(unsigned*)(g_ABhi + o23) = (unsigned)h2 | ((unsigned)h3 << 16);
            *(unsigned*)(g_ABlo + o23) = (unsigned)l2 | ((unsigned)l3 << 16);
        }
    }
}

// ---------------------------------------------------------------------------
// nt_invert_mask: fused NT-GEMM (S or R) + mask + blocked GJ inversion.
// grid 48 x 512 threads.
//  CTA id 0..31:  mode = id&1, b = id>>1 : S = P P^T + regI -> smem M,
//                 then mask -> g_D, then invert -> g_Sinv.
//  CTA id 32..47: mode 2, b = id-32 : R = B A^T -> g_R, g_RT; exit.
// 16-warp GEMM: warp tile 32x32 (wm=(wid&3)*32, wn=(wid>>2)*32).
// ---------------------------------------------------------------------------
#define MST 132
#define CST 36
#define TST 36
#define FUSED_SMEM (1024 + 1024 + 3 * STAGE_SZ)   // 198656; invert region 90624 fits inside

__global__ void __launch_bounds__(512, 1)
nt_invert_mask(const float* __restrict__ evx, const float* __restrict__ evy,
               const float* __restrict__ ax,  const float* __restrict__ ay) {
    extern __shared__ char smraw[];
    char* alignedp = smraw + ((unsigned)(1024 - (smem_u32(smraw) & 1023)) & 1023);
    unsigned base = smem_u32(alignedp);
    int tid = threadIdx.x, wid = tid >> 5, lane = tid & 31;
    int id = blockIdx.x;
    int b, mode;
    if (id < 32) { b = id >> 1; mode = id & 1; }
    else         { b = id - 32; mode = 2; }

    size_t offA = (size_t)b * KK * DD;
    size_t offB = (size_t)(BB + b) * KK * DD;
    size_t offP = (mode == 0) ? offA : offB;
    size_t offQ = (mode == 1) ? offB : offA;
    const __nv_bfloat16* Ph = g_ABhi + offP;
    const __nv_bfloat16* Pl = g_ABlo + offP;
    const __nv_bfloat16* Qh = g_ABhi + offQ;
    const __nv_bfloat16* Ql = g_ABlo + offQ;

    int wm = (wid & 3) * 32, wn = (wid >> 2) * 32;

    float acc[2][4][4];
#pragma unroll
    for (int mt = 0; mt < 2; mt++)
#pragma unroll
        for (int nt = 0; nt < 4; nt++)
#pragma unroll
            for (int i = 0; i < 4; i++) acc[mt][nt][i] = 0.0f;

    unsigned msk = (unsigned)((lane & 7) << 4);
    unsigned a_c0 = (unsigned)((lane >> 4) * 16);
    unsigned b_c0 = (unsigned)(((lane >> 3) & 1) * 16);
    unsigned a_row[2], b_row[2];
#pragma unroll
    for (int mt = 0; mt < 2; mt++)
        a_row[mt] = (unsigned)((wm + mt * 16 + (lane & 15)) * 128);
#pragma unroll
    for (int np = 0; np < 2; np++)
        b_row[np] = (unsigned)((wn + np * 16 + ((lane >> 4) << 3) + (lane & 7)) * 128);

    auto issue = [&](int c) {
        unsigned stage = base + 1024 + (unsigned)(c % 3) * STAGE_SZ;
        int k0 = c * 64;
#pragma unroll
        for (int u = 0; u < 8; u++) {
            int tile = u >> 1;
            int v = tid + (u & 1) * 512;
            int r = v >> 3, s = v & 7;
            unsigned sa = stage + tile * 16384 + SWZ((unsigned)(r * 128 + s * 16));
            const __nv_bfloat16* g;
            if (tile == 0)      g = Ph;
            else if (tile == 1) g = Pl;
            else if (tile == 2) g = Qh;
            else                g = Ql;
            g += (size_t)r * DD + k0 + s * 8;
            asm volatile("cp.async.cg.shared.global [%0], [%1], 16;"
                         :: "r"(sa), "l"(g) : "memory");
        }
        asm volatile("cp.async.commit_group;" ::: "memory");
    };

    issue(0);
    issue(1);
    for (int c = 0; c < 8; c++) {
        if (c < 7)
            asm volatile("cp.async.wait_group 1;" ::: "memory");
        else
            asm volatile("cp.async.wait_group 0;" ::: "memory");
        __syncthreads();
        if (c + 2 < 8) issue(c + 2);
        unsigned stage = base + 1024 + (unsigned)(c % 3) * STAGE_SZ;
        unsigned sAh = stage, sAl = stage + 16384, sBh = stage + 32768, sBl = stage + 49152;
#pragma unroll
        for (int kk = 0; kk < 4; kk++) {
            unsigned ca = (a_c0 + (unsigned)(kk * 32)) ^ msk;
            unsigned cb = (b_c0 + (unsigned)(kk * 32)) ^ msk;
            unsigned ah[2][4], al[2][4], bh[2][4], bl[2][4];
#pragma unroll
            for (int mt = 0; mt < 2; mt++) {
                ldm4(ah[mt], sAh + a_row[mt] + ca);
                ldm4(al[mt], sAl + a_row[mt] + ca);
            }
#pragma unroll
            for (int np = 0; np < 2; np++) {
                ldm4(bh[np], sBh + b_row[np] + cb);
                ldm4(bl[np], sBl + b_row[np] + cb);
            }
#pragma unroll
            for (int mt = 0; mt < 2; mt++)
#pragma unroll
                for (int nt = 0; nt < 4; nt++)
                    mma_bf16(acc[mt][nt], ah[mt], &bh[nt >> 1][(nt & 1) * 2]);
#pragma unroll
            for (int mt = 0; mt < 2; mt++)
#pragma unroll
                for (int nt = 0; nt < 4; nt++)
                    mma_bf16(acc[mt][nt], ah[mt], &bl[nt >> 1][(nt & 1) * 2]);
#pragma unroll
            for (int mt = 0; mt < 2; mt++)
#pragma unroll
                for (int nt = 0; nt < 4; nt++)
                    mma_bf16(acc[mt][nt], al[mt], &bh[nt >> 1][(nt & 1) * 2]);
        }
    }

    if (mode == 2) {
        float* C  = g_R  + (size_t)b * KK * KK;
        float* CT = g_RT + (size_t)b * KK * KK;
#pragma unroll
        for (int mt = 0; mt < 2; mt++) {
#pragma unroll
            for (int nt = 0; nt < 4; nt++) {
                int r0 = wm + mt * 16 + (lane >> 2);
                int c0 = wn + nt * 8 + (lane & 3) * 2;
                float v0 = acc[mt][nt][0], v1 = acc[mt][nt][1];
                float v2 = acc[mt][nt][2], v3 = acc[mt][nt][3];
                C[r0 * KK + c0] = v0;
                C[r0 * KK + c0 + 1] = v1;
                C[(r0 + 8) * KK + c0] = v2;
                C[(r0 + 8) * KK + c0 + 1] = v3;
                CT[c0 * KK + r0] = v0;
                CT[(c0 + 1) * KK + r0] = v1;
                CT[c0 * KK + r0 + 8] = v2;
                CT[(c0 + 1) * KK + r0 + 8] = v3;
            }
        }
        return;
    }

    // ===== S epilogue into smem M (stage data dead after sync) =====
    float* M  = (float*)alignedp;
    float* Cs = M + 128 * MST;
    float* T  = Cs + 128 * CST;
    __syncthreads();
#pragma unroll
    for (int mt = 0; mt < 2; mt++) {
#pragma unroll
        for (int nt = 0; nt < 4; nt++) {
            int r0 = wm + mt * 16 + (lane >> 2);
            int c0 = wn + nt * 8 + (lane & 3) * 2;
            float v0 = acc[mt][nt][0], v1 = acc[mt][nt][1];
            float v2 = acc[mt][nt][2], v3 = acc[mt][nt][3];
            if (r0 == c0) v0 += REGC;
            if (r0 == c0 + 1) v1 += REGC;
            if (r0 + 8 == c0) v2 += REGC;
            if (r0 + 8 == c0 + 1) v3 += REGC;
            M[r0 * MST + c0] = v0;
            M[r0 * MST + c0 + 1] = v1;
            M[(r0 + 8) * MST + c0] = v2;
            M[(r0 + 8) * MST + c0 + 1] = v3;
        }
    }

    // ===== mask =====
    int dir = mode;   // id = b*2+dir matches g_D/g_Sinv indexing
    {
        __shared__ float t1[128], u1[128], t2[128], u2[128];
        __shared__ float v1[128], w1[128], v2[128], w2[128];
        __shared__ float red[128];
        __shared__ float sc_main, sc_aux;

        const float* e1p = (dir ? evy : evx) + b * KK;
        const float* e2p = (dir ? evx : evy) + b * KK;
        const float* a1p = (dir ? ay : ax) + b * KK;
        const float* a2p = (dir ? ax : ay) + b * KK;

        float e1 = 0.f, e2 = 0.f, q1 = 0.f, q2 = 0.f;
        if (tid < 128) {
            e1 = fmaxf(e1p[tid], 1e-10f);
            e2 = fmaxf(e2p[tid], 1e-10f);
            q1 = fmaxf(a1p[tid], 1e-10f);
            q2 = fmaxf(a2p[tid], 1e-10f);
            red[tid] = fmaxf(e1, e2);
        }
        __syncthreads();
        for (int off = 64; off; off >>= 1) {
            if (tid < off) red[tid] = fmaxf(red[tid], red[tid + off]);
            __syncthreads();
        }
        if (tid == 0) sc_main = fmaxf(red[0], 1e-10f);
        __syncthreads();
        if (tid < 128) red[tid] = fmaxf(q1, q2);
        __syncthreads();
        for (int off = 64; off; off >>= 1) {
            if (tid < off) red[tid] = fmaxf(red[tid], red[tid + off]);
            __syncthreads();
        }
        if (tid == 0) sc_aux = fmaxf(red[0], 1e-10f);
        __syncthreads();

        if (tid < 128) {
            float r, d;
            r = e1 / sc_main; d = r + 1.0f; t1[tid] = sqrtf(r) / d; u1[tid] = 1.0f / d;
            r = e2 / sc_main; d = r + 1.0f; t2[tid] = sqrtf(r) / d; u2[tid] = 1.0f / d;
            r = q1 / sc_aux;  d = r + 1.0f; v1[tid] = sqrtf(r) / d; w1[tid] = 1.0f / d;
            r = q2 / sc_aux;  d = r + 1.0f; v2[tid] = sqrtf(r) / d; w2[tid] = 1.0f / d;
        }
        __syncthreads();

        float* Dp = g_D + (size_t)id * (KK * KK);
        for (int v = tid; v < KK * KK; v += 512) {
            int i = v >> 7, j = v & 127;
            float mr = t2[i] - t1[j], mi = u2[i] - u1[j];
            float ar = v2[i] - v1[j], ai = w2[i] - w1[j];
            Dp[v] = 100.0f * (mr * mr + mi * mi) + 25.0f * (ar * ar + ai * ai);
        }
    }
    __syncthreads();

    // ===== inversion (M already in smem) =====
    int tx = tid & 15, ty = tid >> 4;
    float* Si = g_Sinv + (size_t)id * KK * KK;

    for (int p = 0; p < 4; p++) {
        int p0 = p * 32;
        // warp 0: register GJ on pivot block; other warps copy Cs concurrently
        if (tid < 32) {
            float reg[32];
#pragma unroll
            for (int i = 0; i < 32; i++)
                reg[i] = M[(p0 + i) * MST + p0 + lane];
#pragma unroll
            for (int j = 0; j < 32; j++) {
                float piv = __shfl_sync(0xffffffffu, reg[j], j);
                float pivinv = 1.0f / piv;
                float rowj = (lane == j) ? pivinv : reg[j] * pivinv;
#pragma unroll
                for (int i = 0; i < 32; i++) {
                    if (i == j) continue;
                    float f = __shfl_sync(0xffffffffu, reg[i], j);
                    reg[i] = (lane == j) ? (-f * pivinv) : fmaf(-f, rowj, reg[i]);
                }
                reg[j] = rowj;
            }
#pragma unroll
            for (int i = 0; i < 32; i++)
                T[i * TST + lane] = reg[i];
        } else {
            for (int v = tid - 32; v < 1024; v += 480) {
                int i = v >> 3, q4 = (v & 7) << 2;
                *(float4*)(Cs + i * CST + q4) = *(const float4*)(M + i * MST + p0 + q4);
            }
        }
        __syncthreads();

        // row panel: M[P,:] <- T * Mold[P,:]; M[P,P] <- T
        {
            int qr = ty;
            int cb = tx * 8;
            float out[8];
#pragma unroll
            for (int a = 0; a < 8; a++) out[a] = 0.0f;
            for (int r = 0; r < 32; r++) {
                float tq = T[qr * TST + r];
                const float* Mr = M + (p0 + r) * MST + cb;
#pragma unroll
                for (int a = 0; a < 8; a += 4) {
                    float4 mv = *(const float4*)(Mr + a);
                    out[a + 0] += tq * mv.x;
                    out[a + 1] += tq * mv.y;
                    out[a + 2] += tq * mv.z;
                    out[a + 3] += tq * mv.w;
                }
            }
            __syncthreads();
#pragma unroll
            for (int a = 0; a < 8; a++) {
                int l = cb + a;
                float vv = (l >= p0 && l < p0 + 32) ? T[qr * TST + (l - p0)] : out[a];
                M[(p0 + qr) * MST + l] = vv;
            }
            __syncthreads();
        }

        // rank-32 update: 96 rows x 128 cols; thread does 3 rows x 8 cols
        {
            ull acc2[3][4];
#pragma unroll
            for (int r = 0; r < 3; r++)
#pragma unroll
                for (int c = 0; c < 4; c++) acc2[r][c] = 0ULL;
            for (int q = 0; q < 32; q++) {
                const float* Mp = M + (p0 + q) * MST + tx * 8;
                ull b0 = *(const ull*)(Mp + 0);
                ull b1 = *(const ull*)(Mp + 2);
                ull b2 = *(const ull*)(Mp + 4);
                ull b3 = *(const ull*)(Mp + 6);
#pragma unroll
                for (int r = 0; r < 3; r++) {
                    int z = ty + 32 * r;
                    int i = (z < p0) ? z : z + 32;
                    float av = Cs[i * CST + q];
                    ull a2 = pack2(av, av);
                    ffma2(acc2[r][0], a2, b0);
                    ffma2(acc2[r][1], a2, b1);
                    ffma2(acc2[r][2], a2, b2);
                    ffma2(acc2[r][3], a2, b3);
                }
            }
#pragma unroll
            for (int r = 0; r < 3; r++) {
                int z = ty + 32 * r;
                int i = (z < p0) ? z : z + 32;
#pragma unroll
                for (int c = 0; c < 4; c++) {
                    int l = tx * 8 + 2 * c;
                    float lo, hi;
                    unpack2(acc2[r][c], lo, hi);
                    float* Mp = M + i * MST + l;
                    bool inP0 = (l >= p0 && l < p0 + 32);
                    bool inP1 = (l + 1 >= p0 && l + 1 < p0 + 32);
                    float o0 = (inP0 ? 0.0f : Mp[0]) - lo;
                    float o1 = (inP1 ? 0.0f : Mp[1]) - hi;
                    Mp[0] = o0;
                    Mp[1] = o1;
                }
            }
            __syncthreads();
        }
    }

#pragma unroll
    for (int u = 0; u < 8; u++) {
        int v = tid + u * 512;
        int m = v >> 5, c4 = (v & 31) << 2;
        *(float4*)(Si + m * 128 + c4) = *(const float4*)(M + m * MST + c4);
    }
}

// ---------------------------------------------------------------------------
// solve_gemm (unchanged)
// ---------------------------------------------------------------------------
#define EST 20
#define SST 68
__global__ void solve_gemm(float* __restrict__ out, int mode) {
    int id = blockIdx.y;
    int b = id >> 1, dir = id & 1;
    int n0 = blockIdx.x * 64;
    const float* Si = g_Sinv + (size_t)id * (KK * KK);
    const float* Dm = g_D + (size_t)id * (KK * KK);
    const float* Rb = (dir ? g_RT : g_R) + (size_t)b * (KK * KK);
    const float* Xp = (mode == 1 ? g_X0 : g_X1) + (size_t)id * (KK * KK);
    const float* base = g_X0 + (size_t)id * (KK * KK);
    float* Cout;
    if (mode == 0)      Cout = g_X0 + (size_t)id * (KK * KK);
    else if (mode == 1) Cout = g_X1 + (size_t)id * (KK * KK);
    else                Cout = out + (size_t)(dir ? BB * KK * KK : 0) + (size_t)b * (KK * KK);

    __shared__ float Ts[128 * EST];
    __shared__ float Ss[16 * SST];

    int tid = threadIdx.x;
    int ty = tid >> 4, tx = tid & 15;
    int v0 = tid, v1 = tid + 256;
    int tm0 = v0 >> 2, tc0 = (v0 & 3) << 2;
    int tm1 = v1 >> 2, tc1 = (v1 & 3) << 2;
    int sk = tid >> 4, sc = (tid & 15) << 2;

    ull acc[8][2];
#pragma unroll
    for (int r = 0; r < 8; r++) { acc[r][0] = 0ULL; acc[r][1] = 0ULL; }

    for (int k0 = 0; k0 < KK; k0 += 16) {
        if (mode == 0) {
            *(float4*)&Ts[tm0 * EST + tc0] = *(const float4*)(Rb + tm0 * 128 + k0 + tc0);
            *(float4*)&Ts[tm1 * EST + tc1] = *(const float4*)(Rb + tm1 * 128 + k0 + tc1);
        } else {
            float4 d0 = *(const float4*)(Dm + tm0 * 128 + k0 + tc0);
            float4 x0 = *(const float4*)(Xp + tm0 * 128 + k0 + tc0);
            float4 d1 = *(const float4*)(Dm + tm1 * 128 + k0 + tc1);
            float4 x1 = *(const float4*)(Xp + tm1 * 128 + k0 + tc1);
            float4 o0 = make_float4(d0.x * x0.x, d0.y * x0.y, d0.z * x0.z, d0.w * x0.w);
            float4 o1 = make_float4(d1.x * x1.x, d1.y * x1.y, d1.z * x1.z, d1.w * x1.w);
            *(float4*)&Ts[tm0 * EST + tc0] = o0;
            *(float4*)&Ts[tm1 * EST + tc1] = o1;
        }
        *(float4*)&Ss[sk * SST + sc] = *(const float4*)(Si + (size_t)(k0 + sk) * 128 + n0 + sc);
        __syncthreads();
#pragma unroll
        for (int k = 0; k < 16; k++) {
            ull b0 = *(const ull*)&Ss[k * SST + tx * 4];
            ull b1 = *(const ull*)&Ss[k * SST + tx * 4 + 2];
#pragma unroll
            for (int r = 0; r < 8; r++) {
                float av = Ts[(ty * 8 + r) * EST + k];
                ull a2 = pack2(av, av);
                ffma2(acc[r][0], a2, b0);
                ffma2(acc[r][1], a2, b1);
            }
        }
        __syncthreads();
    }
#pragma unroll
    for (int r = 0; r < 8; r++) {
        int m = ty * 8 + r;
#pragma unroll
        for (int c2 = 0; c2 < 2; c2++) {
            int n = n0 + tx * 4 + 2 * c2;
            int idx = m * 128 + n;
            float lo, hi;
            unpack2(acc[r][c2], lo, hi);
            if (mode != 0) {
                lo = base[idx] - lo;
                hi = base[idx + 1] - hi;
            }
            Cout[idx] = lo;
            Cout[idx + 1] = hi;
        }
    }
}

// ---------------------------------------------------------------------------
extern "C" void kernel_launch(void* const* d_in, const int* in_sizes, int n_in,
                              void* d_out, int out_size) {
    const float* feat_x  = (const float*)d_in[0];
    const float* feat_y  = (const float*)d_in[1];
    const float* evals_x = (const float*)d_in[2];
    const float* evals_y = (const float*)d_in[3];
    const float* evecs_x = (const float*)d_in[4];
    const float* evecs_y = (const float*)d_in[5];
    const float* aux_x   = (const float*)d_in[6];
    const float* aux_y   = (const float*)d_in[7];
    float* out = (float*)d_out;

    split_E<<<dim3(8192, 2), 256>>>(evecs_x, evecs_y);

    cudaFuncSetAttribute(mma_proj, cudaFuncAttributeMaxDynamicSharedMemorySize, MMA_SMEM);
    mma_proj<<<dim3(4, 32), 256, MMA_SMEM>>>(feat_x, feat_y);

    cudaFuncSetAttribute(nt_invert_mask, cudaFuncAttributeMaxDynamicSharedMemorySize, FUSED_SMEM);
    nt_invert_mask<<<48, 512, FUSED_SMEM>>>(evals_x, evals_y, aux_x, aux_y);

    solve_gemm<<<dim3(2, 32), 256>>>(out, 0);
    solve_gemm<<<dim3(2, 32), 256>>>(out, 1);
    solve_gemm<<<dim3(2, 32), 256>>>(out, 2);
}

// round 12
// speedup vs baseline: 1.0374x; 1.0374x over previous
#include <cuda_runtime.h>
#include <cuda_bf16.h>

#define BB 16
#define NN 4096
#define DD 512
#define KK 128
#define REGC 1e-6f

typedef unsigned long long ull;

__device__ __forceinline__ ull pack2(float x, float y) {
    ull r; asm("mov.b64 %0, {%1, %2};" : "=l"(r) : "f"(x), "f"(y)); return r;
}
__device__ __forceinline__ void unpack2(ull v, float& lo, float& hi) {
    asm("mov.b64 {%0, %1}, %2;" : "=f"(lo), "=f"(hi) : "l"(v));
}
__device__ __forceinline__ void ffma2(ull& d, ull a, ull b) {
    asm("fma.rn.f32x2 %0, %1, %2, %0;" : "+l"(d) : "l"(a), "l"(b));
}
__device__ __forceinline__ unsigned smem_u32(const void* p) {
    unsigned a;
    asm("{ .reg .u64 t; cvta.to.shared.u64 t, %1; cvt.u32.u64 %0, t; }" : "=r"(a) : "l"(p));
    return a;
}
__device__ __forceinline__ void ldm4(unsigned* r, unsigned addr) {
    asm volatile("ldmatrix.sync.aligned.m8n8.x4.shared.b16 {%0,%1,%2,%3}, [%4];"
                 : "=r"(r[0]), "=r"(r[1]), "=r"(r[2]), "=r"(r[3]) : "r"(addr));
}
__device__ __forceinline__ void mma_bf16(float* d, const unsigned* a, const unsigned* b) {
    asm volatile(
        "mma.sync.aligned.m16n8k16.row.col.f32.bf16.bf16.f32 "
        "{%0,%1,%2,%3}, {%4,%5,%6,%7}, {%8,%9}, {%0,%1,%2,%3};"
        : "+f"(d[0]), "+f"(d[1]), "+f"(d[2]), "+f"(d[3])
        : "r"(a[0]), "r"(a[1]), "r"(a[2]), "r"(a[3]), "r"(b[0]), "r"(b[1]));
}
__device__ __forceinline__ float lds_f32(unsigned a) {
    float v; asm volatile("ld.shared.f32 %0, [%1];" : "=f"(v) : "r"(a)); return v;
}
__device__ __forceinline__ void sts128(unsigned a, unsigned r0, unsigned r1,
                                       unsigned r2, unsigned r3) {
    asm volatile("st.shared.v4.b32 [%0], {%1,%2,%3,%4};"
                 :: "r"(a), "r"(r0), "r"(r1), "r"(r2), "r"(r3) : "memory");
}
#define SWZ(o) ((o) ^ (((o) >> 3) & 0x70))

// Scratch
__device__ float g_S[2 * BB * KK * KK];
__device__ float g_Sinv[2 * BB * KK * KK];
__device__ float g_R[BB * KK * KK];
__device__ float g_RT[BB * KK * KK];
__device__ float g_D[2 * BB * KK * KK];
__device__ __nv_bfloat16 g_Ehi[2 * BB * KK * NN];
__device__ __nv_bfloat16 g_Elo[2 * BB * KK * NN];
__device__ __nv_bfloat16 g_ABhi[2 * BB * KK * DD];
__device__ __nv_bfloat16 g_ABlo[2 * BB * KK * DD];

__device__ __forceinline__ void split1(float x, unsigned short& h, unsigned short& l) {
    __nv_bfloat16 hb = __float2bfloat16_rn(x);
    float r = x - __bfloat162float(hb);
    __nv_bfloat16 lb = __float2bfloat16_rn(r);
    h = __bfloat16_as_ushort(hb);
    l = __bfloat16_as_ushort(lb);
}

// ---------------------------------------------------------------------------
// split_E (unchanged)
// ---------------------------------------------------------------------------
__global__ void split_E(const float* __restrict__ ex, const float* __restrict__ ey) {
    int w = blockIdx.y;
    const float* E = w ? ey : ex;
    size_t i4 = (size_t)blockIdx.x * 256 + threadIdx.x;
    float4 t = *((const float4*)E + i4);
    unsigned short h0, h1, h2, h3, l0, l1, l2, l3;
    split1(t.x, h0, l0); split1(t.y, h1, l1); split1(t.z, h2, l2); split1(t.w, h3, l3);
    ull hp = (ull)h0 | ((ull)h1 << 16) | ((ull)h2 << 32) | ((ull)h3 << 48);
    ull lp = (ull)l0 | ((ull)l1 << 16) | ((ull)l2 << 32) | ((ull)l3 << 48);
    size_t o = (size_t)w * (BB * KK * NN) + i4 * 4;
    *(ull*)(g_Ehi + o) = hp;
    *(ull*)(g_Elo + o) = lp;
}

// ---------------------------------------------------------------------------
// mma_proj (unchanged from R10)
// ---------------------------------------------------------------------------
#define CONV_BH 0
#define CONV_BL 16384
#define STAGE0 32768
#define STAGE_SZ 65536
#define MMA_SMEM (1024 + STAGE0 + 3 * STAGE_SZ)

__global__ void __launch_bounds__(256, 1) mma_proj(const float* __restrict__ fx,
                                                   const float* __restrict__ fy) {
    extern __shared__ char smraw[];
    unsigned base = (smem_u32(smraw) + 1023) & ~1023u;
    int tid = threadIdx.x, wid = tid >> 5, lane = tid & 31;

    int p = blockIdx.y; int w = p >> 4, b = p & 15;
    int n0 = blockIdx.x * 128;
    const __nv_bfloat16* Eh = g_Ehi + (size_t)p * KK * NN;
    const __nv_bfloat16* El = g_Elo + (size_t)p * KK * NN;
    const float* Ff = (w ? fy : fx) + (size_t)b * NN * DD + n0;
    size_t cbase = (size_t)p * KK * DD + n0;

    int wm = (wid & 1) * 64, wn = (wid >> 1) * 32;

    float acc[4][4][4];
#pragma unroll
    for (int mt = 0; mt < 4; mt++)
#pragma unroll
        for (int nt = 0; nt < 4; nt++)
#pragma unroll
            for (int i = 0; i < 4; i++) acc[mt][nt][i] = 0.0f;

    unsigned msk = (unsigned)((lane & 7) << 4);
    unsigned a_c0 = (unsigned)((lane >> 4) * 16);
    unsigned b_c0 = (unsigned)(((lane >> 3) & 1) * 16);
    unsigned a_row[4], b_row[2];
#pragma unroll
    for (int mt = 0; mt < 4; mt++)
        a_row[mt] = (unsigned)((wm + mt * 16 + (lane & 15)) * 128);
#pragma unroll
    for (int np = 0; np < 2; np++)
        b_row[np] = (unsigned)((wn + np * 16 + ((lane >> 4) << 3) + (lane & 7)) * 128);

    int cd = tid & 127, ckg = tid >> 7;

    auto issue = [&](int c) {
        unsigned stage = base + STAGE0 + (unsigned)(c % 3) * STAGE_SZ;
        int k0 = c * 64;
#pragma unroll
        for (int u = 0; u < 8; u++) {
            int tile = u >> 2;
            int v = tid + (u & 3) * 256;
            int r = v >> 3, s = v & 7;
            unsigned sa = stage + tile * 16384 + SWZ((unsigned)(r * 128 + s * 16));
            const __nv_bfloat16* g = (tile ? El : Eh) + (size_t)r * NN + k0 + s * 8;
            asm volatile("cp.async.cg.shared.global [%0], [%1], 16;"
                         :: "r"(sa), "l"(g) : "memory");
        }
#pragma unroll
        for (int u = 0; u < 8; u++) {
            int v = tid + u * 256;
            int r = v >> 5, s = v & 31;
            unsigned sa = stage + 32768 + (unsigned)(r * 512 + s * 16);
            const float* g = Ff + (size_t)(k0 + r) * DD + s * 4;
            asm volatile("cp.async.cg.shared.global [%0], [%1], 16;"
                         :: "r"(sa), "l"(g) : "memory");
        }
        asm volatile("cp.async.commit_group;" ::: "memory");
    };

    issue(0);
    issue(1);
    for (int c = 0; c < 64; c++) {
        if (c < 63)
            asm volatile("cp.async.wait_group 1;" ::: "memory");
        else
            asm volatile("cp.async.wait_group 0;" ::: "memory");
        __syncthreads();

        unsigned stage = base + STAGE0 + (unsigned)(c % 3) * STAGE_SZ;
        {
            unsigned fpb = stage + 32768;
#pragma unroll
            for (int kq = 0; kq < 4; kq++) {
                int kstart = ckg * 8 + kq * 16;
                unsigned hw[4], lw[4];
#pragma unroll
                for (int w2 = 0; w2 < 4; w2++) {
                    float x0 = lds_f32(fpb + (unsigned)(((kstart + 2 * w2) * 128 + cd) * 4));
                    float x1 = lds_f32(fpb + (unsigned)(((kstart + 2 * w2 + 1) * 128 + cd) * 4));
                    unsigned short h0, l0, h1, l1;
                    split1(x0, h0, l0); split1(x1, h1, l1);
                    hw[w2] = (unsigned)h0 | ((unsigned)h1 << 16);
                    lw[w2] = (unsigned)l0 | ((unsigned)l1 << 16);
                }
                unsigned off = SWZ((unsigned)(cd * 128 + kstart * 2));
                sts128(base + CONV_BH + off, hw[0], hw[1], hw[2], hw[3]);
                sts128(base + CONV_BL + off, lw[0], lw[1], lw[2], lw[3]);
            }
        }
        __syncthreads();
        if (c + 2 < 64) issue(c + 2);

        unsigned sAh = stage, sAl = stage + 16384;
        unsigned sBh = base + CONV_BH, sBl = base + CONV_BL;
#pragma unroll
        for (int kk = 0; kk < 4; kk++) {
            unsigned ca = (a_c0 + (unsigned)(kk * 32)) ^ msk;
            unsigned cb = (b_c0 + (unsigned)(kk * 32)) ^ msk;
            unsigned ah[4][4], al[4][4], bh[2][4], bl[2][4];
#pragma unroll
            for (int mt = 0; mt < 4; mt++) {
                ldm4(ah[mt], sAh + a_row[mt] + ca);
                ldm4(al[mt], sAl + a_row[mt] + ca);
            }
#pragma unroll
            for (int np = 0; np < 2; np++) {
                ldm4(bh[np], sBh + b_row[np] + cb);
                ldm4(bl[np], sBl + b_row[np] + cb);
            }
#pragma unroll
            for (int mt = 0; mt < 4; mt++)
#pragma unroll
                for (int nt = 0; nt < 4; nt++)
                    mma_bf16(acc[mt][nt], ah[mt], &bh[nt >> 1][(nt & 1) * 2]);
#pragma unroll
            for (int mt = 0; mt < 4; mt++)
#pragma unroll
                for (int nt = 0; nt < 4; nt++)
                    mma_bf16(acc[mt][nt], ah[mt], &bl[nt >> 1][(nt & 1) * 2]);
#pragma unroll
            for (int mt = 0; mt < 4; mt++)
#pragma unroll
                for (int nt = 0; nt < 4; nt++)
                    mma_bf16(acc[mt][nt], al[mt], &bh[nt >> 1][(nt & 1) * 2]);
        }
    }

#pragma unroll
    for (int mt = 0; mt < 4; mt++) {
#pragma unroll
        for (int nt = 0; nt < 4; nt++) {
            int r0 = wm + mt * 16 + (lane >> 2);
            int c0 = wn + nt * 8 + (lane & 3) * 2;
            unsigned short h0, l0, h1, l1, h2, l2, h3, l3;
            split1(acc[mt][nt][0], h0, l0);
            split1(acc[mt][nt][1], h1, l1);
            split1(acc[mt][nt][2], h2, l2);
            split1(acc[mt][nt][3], h3, l3);
            size_t o01 = cbase + (size_t)r0 * DD + c0;
            size_t o23 = cbase + (size_t)(r0 + 8) * DD + c0;
            *(unsigned*)(g_ABhi + o01) = (unsigned)h0 | ((unsigned)h1 << 16);
            *(unsigned*)(g_ABlo + o01) = (unsigned)l0 | ((unsigned)l1 << 16);
            *(unsigned*)(g_ABhi + o23) = (unsigned)h2 | ((unsigned)h3 << 16);
            *(unsigned*)(g_ABlo + o23) = (unsigned)l2 | ((unsigned)l3 << 16);
        }
    }
}

// ---------------------------------------------------------------------------
// gemm_nt_hmma (R10 version, 48 CTAs x 256 thr)
// ---------------------------------------------------------------------------
#define NTSTAGE_BYTES 65536
#define NT_SMEM (1024 + 3 * NTSTAGE_BYTES)
__global__ void __launch_bounds__(256, 1) gemm_nt_hmma() {
    extern __shared__ char smraw[];
    unsigned base = (smem_u32(smraw) + 1023) & ~1023u;
    int tid = threadIdx.x, wid = tid >> 5, lane = tid & 31;

    int id = blockIdx.x;
    int b = id / 3, mode = id % 3;
    size_t offA = (size_t)b * KK * DD;
    size_t offB = (size_t)(BB + b) * KK * DD;
    size_t offP = (mode == 0) ? offA : offB;
    size_t offQ = (mode == 1) ? offB : offA;
    const __nv_bfloat16* Ph = g_ABhi + offP;
    const __nv_bfloat16* Pl = g_ABlo + offP;
    const __nv_bfloat16* Qh = g_ABhi + offQ;
    const __nv_bfloat16* Ql = g_ABlo + offQ;
    float* C = (mode < 2) ? g_S + (size_t)(b * 2 + mode) * KK * KK
                          : g_R + (size_t)b * KK * KK;
    float* CT = g_RT + (size_t)b * KK * KK;

    int wm = (wid & 1) * 64, wn = (wid >> 1) * 32;

    float acc[4][4][4];
#pragma unroll
    for (int mt = 0; mt < 4; mt++)
#pragma unroll
        for (int nt = 0; nt < 4; nt++)
#pragma unroll
            for (int i = 0; i < 4; i++) acc[mt][nt][i] = 0.0f;

    unsigned msk = (unsigned)((lane & 7) << 4);
    unsigned a_c0 = (unsigned)((lane >> 4) * 16);
    unsigned b_c0 = (unsigned)(((lane >> 3) & 1) * 16);
    unsigned a_row[4], b_row[2];
#pragma unroll
    for (int mt = 0; mt < 4; mt++)
        a_row[mt] = (unsigned)((wm + mt * 16 + (lane & 15)) * 128);
#pragma unroll
    for (int np = 0; np < 2; np++)
        b_row[np] = (unsigned)((wn + np * 16 + ((lane >> 4) << 3) + (lane & 7)) * 128);

    auto issue = [&](int c) {
        unsigned stage = base + 1024 + (unsigned)(c % 3) * NTSTAGE_BYTES;
        int k0 = c * 64;
#pragma unroll
        for (int u = 0; u < 16; u++) {
            int tile = u >> 2;
            int v = tid + (u & 3) * 256;
            int r = v >> 3, s = v & 7;
            unsigned sa = stage + tile * 16384 + SWZ((unsigned)(r * 128 + s * 16));
            const __nv_bfloat16* g;
            if (tile == 0)      g = Ph;
            else if (tile == 1) g = Pl;
            else if (tile == 2) g = Qh;
            else                g = Ql;
            g += (size_t)r * DD + k0 + s * 8;
            asm volatile("cp.async.cg.shared.global [%0], [%1], 16;"
                         :: "r"(sa), "l"(g) : "memory");
        }
        asm volatile("cp.async.commit_group;" ::: "memory");
    };

    issue(0);
    issue(1);
    for (int c = 0; c < 8; c++) {
        if (c < 7)
            asm volatile("cp.async.wait_group 1;" ::: "memory");
        else
            asm volatile("cp.async.wait_group 0;" ::: "memory");
        __syncthreads();
        if (c + 2 < 8) issue(c + 2);
        unsigned stage = base + 1024 + (unsigned)(c % 3) * NTSTAGE_BYTES;
        unsigned sAh = stage, sAl = stage + 16384, sBh = stage + 32768, sBl = stage + 49152;
#pragma unroll
        for (int kk = 0; kk < 4; kk++) {
            unsigned ca = (a_c0 + (unsigned)(kk * 32)) ^ msk;
            unsigned cb = (b_c0 + (unsigned)(kk * 32)) ^ msk;
            unsigned ah[4][4], al[4][4], bh[2][4], bl[2][4];
#pragma unroll
            for (int mt = 0; mt < 4; mt++) {
                ldm4(ah[mt], sAh + a_row[mt] + ca);
                ldm4(al[mt], sAl + a_row[mt] + ca);
            }
#pragma unroll
            for (int np = 0; np < 2; np++) {
                ldm4(bh[np], sBh + b_row[np] + cb);
                ldm4(bl[np], sBl + b_row[np] + cb);
            }
#pragma unroll
            for (int mt = 0; mt < 4; mt++)
#pragma unroll
                for (int nt = 0; nt < 4; nt++)
                    mma_bf16(acc[mt][nt], ah[mt], &bh[nt >> 1][(nt & 1) * 2]);
#pragma unroll
            for (int mt = 0; mt < 4; mt++)
#pragma unroll
                for (int nt = 0; nt < 4; nt++)
                    mma_bf16(acc[mt][nt], ah[mt], &bl[nt >> 1][(nt & 1) * 2]);
#pragma unroll
            for (int mt = 0; mt < 4; mt++)
#pragma unroll
                for (int nt = 0; nt < 4; nt++)
                    mma_bf16(acc[mt][nt], al[mt], &bh[nt >> 1][(nt & 1) * 2]);
        }
    }

#pragma unroll
    for (int mt = 0; mt < 4; mt++) {
#pragma unroll
        for (int nt = 0; nt < 4; nt++) {
            int r0 = wm + mt * 16 + (lane >> 2);
            int c0 = wn + nt * 8 + (lane & 3) * 2;
            float v0 = acc[mt][nt][0], v1 = acc[mt][nt][1];
            float v2 = acc[mt][nt][2], v3 = acc[mt][nt][3];
            if (mode < 2) {
                if (r0 == c0) v0 += REGC;
                if (r0 == c0 + 1) v1 += REGC;
                if (r0 + 8 == c0) v2 += REGC;
                if (r0 + 8 == c0 + 1) v3 += REGC;
            }
            C[r0 * KK + c0] = v0;
            C[r0 * KK + c0 + 1] = v1;
            C[(r0 + 8) * KK + c0] = v2;
            C[(r0 + 8) * KK + c0 + 1] = v3;
            if (mode == 2) {
                CT[c0 * KK + r0] = v0;
                CT[(c0 + 1) * KK + r0] = v1;
                CT[c0 * KK + r0 + 8] = v2;
                CT[(c0 + 1) * KK + r0 + 8] = v3;
            }
        }
    }
}

// ---------------------------------------------------------------------------
// invert_mask (R10 version: fused mask + blocked GJ, 512 threads)
// ---------------------------------------------------------------------------
#define MST 132
#define CST 36
#define TST 36
#define INV_SMEM ((128 * MST + 128 * CST + 32 * TST) * 4)

__global__ void __launch_bounds__(512, 1)
invert_mask(const float* __restrict__ evx, const float* __restrict__ evy,
            const float* __restrict__ ax,  const float* __restrict__ ay) {
    extern __shared__ float sm[];
    float* M  = sm;
    float* Cs = sm + 128 * MST;
    float* T  = Cs + 128 * CST;
    int id = blockIdx.x;
    int b = id >> 1, dir = id & 1;
    const float* S = g_S + (size_t)id * KK * KK;
    float* Si = g_Sinv + (size_t)id * KK * KK;
    int tid = threadIdx.x;
    int lane = tid & 31;
    int tx = tid & 15, ty = tid >> 4;

    // mask
    {
        __shared__ float t1[128], u1[128], t2[128], u2[128];
        __shared__ float v1[128], w1[128], v2[128], w2[128];
        __shared__ float red[128];
        __shared__ float sc_main, sc_aux;

        const float* e1p = (dir ? evy : evx) + b * KK;
        const float* e2p = (dir ? evx : evy) + b * KK;
        const float* a1p = (dir ? ay : ax) + b * KK;
        const float* a2p = (dir ? ax : ay) + b * KK;

        float e1 = 0.f, e2 = 0.f, q1 = 0.f, q2 = 0.f;
        if (tid < 128) {
            e1 = fmaxf(e1p[tid], 1e-10f);
            e2 = fmaxf(e2p[tid], 1e-10f);
            q1 = fmaxf(a1p[tid], 1e-10f);
            q2 = fmaxf(a2p[tid], 1e-10f);
            red[tid] = fmaxf(e1, e2);
        }
        __syncthreads();
        for (int off = 64; off; off >>= 1) {
            if (tid < off) red[tid] = fmaxf(red[tid], red[tid + off]);
            __syncthreads();
        }
        if (tid == 0) sc_main = fmaxf(red[0], 1e-10f);
        __syncthreads();
        if (tid < 128) red[tid] = fmaxf(q1, q2);
        __syncthreads();
        for (int off = 64; off; off >>= 1) {
            if (tid < off) red[tid] = fmaxf(red[tid], red[tid + off]);
            __syncthreads();
        }
        if (tid == 0) sc_aux = fmaxf(red[0], 1e-10f);
        __syncthreads();

        if (tid < 128) {
            float r, d;
            r = e1 / sc_main; d = r + 1.0f; t1[tid] = sqrtf(r) / d; u1[tid] = 1.0f / d;
            r = e2 / sc_main; d = r + 1.0f; t2[tid] = sqrtf(r) / d; u2[tid] = 1.0f / d;
            r = q1 / sc_aux;  d = r + 1.0f; v1[tid] = sqrtf(r) / d; w1[tid] = 1.0f / d;
            r = q2 / sc_aux;  d = r + 1.0f; v2[tid] = sqrtf(r) / d; w2[tid] = 1.0f / d;
        }
        __syncthreads();

        float* Dp = g_D + (size_t)id * (KK * KK);
        for (int v = tid; v < KK * KK; v += 512) {
            int i = v >> 7, j = v & 127;
            float mr = t2[i] - t1[j], mi = u2[i] - u1[j];
            float ar = v2[i] - v1[j], ai = w2[i] - w1[j];
            Dp[v] = 100.0f * (mr * mr + mi * mi) + 25.0f * (ar * ar + ai * ai);
        }
    }

    // inversion
#pragma unroll
    for (int u = 0; u < 8; u++) {
        int v = tid + u * 512;
        int m = v >> 5, c4 = (v & 31) << 2;
        *(float4*)(M + m * MST + c4) = *(const float4*)(S + m * 128 + c4);
    }
    __syncthreads();

    for (int p = 0; p < 4; p++) {
        int p0 = p * 32;
#pragma unroll
        for (int u = 0; u < 2; u++) {
            int v = tid + u * 512;
            int i = v >> 3, q4 = (v & 7) << 2;
            *(float4*)(Cs + i * CST + q4) = *(const float4*)(M + i * MST + p0 + q4);
        }
        __syncthreads();

        if (tid < 32) {
            float reg[32];
#pragma unroll
            for (int i = 0; i < 32; i++)
                reg[i] = M[(p0 + i) * MST + p0 + lane];
#pragma unroll
            for (int j = 0; j < 32; j++) {
                float piv = __shfl_sync(0xffffffffu, reg[j], j);
                float pivinv = 1.0f / piv;
                float rowj = (lane == j) ? pivinv : reg[j] * pivinv;
#pragma unroll
                for (int i = 0; i < 32; i++) {
                    if (i == j) continue;
                    float f = __shfl_sync(0xffffffffu, reg[i], j);
                    reg[i] = (lane == j) ? (-f * pivinv) : fmaf(-f, rowj, reg[i]);
                }
                reg[j] = rowj;
            }
#pragma unroll
            for (int i = 0; i < 32; i++)
                T[i * TST + lane] = reg[i];
        }
        __syncthreads();

        {
            int qr = ty;
            int cb = tx * 8;
            float out[8];
#pragma unroll
            for (int a = 0; a < 8; a++) out[a] = 0.0f;
            for (int r = 0; r < 32; r++) {
                float tq = T[qr * TST + r];
                const float* Mr = M + (p0 + r) * MST + cb;
#pragma unroll
                for (int a = 0; a < 8; a += 4) {
                    float4 mv = *(const float4*)(Mr + a);
                    out[a + 0] += tq * mv.x;
                    out[a + 1] += tq * mv.y;
                    out[a + 2] += tq * mv.z;
                    out[a + 3] += tq * mv.w;
                }
            }
            __syncthreads();
#pragma unroll
            for (int a = 0; a < 8; a++) {
                int l = cb + a;
                float vv = (l >= p0 && l < p0 + 32) ? T[qr * TST + (l - p0)] : out[a];
                M[(p0 + qr) * MST + l] = vv;
            }
            __syncthreads();
        }

        {
            ull acc2[3][4];
#pragma unroll
            for (int r = 0; r < 3; r++)
#pragma unroll
                for (int c = 0; c < 4; c++) acc2[r][c] = 0ULL;
            for (int q = 0; q < 32; q++) {
                const float* Mp = M + (p0 + q) * MST + tx * 8;
                ull b0 = *(const ull*)(Mp + 0);
                ull b1 = *(const ull*)(Mp + 2);
                ull b2 = *(const ull*)(Mp + 4);
                ull b3 = *(const ull*)(Mp + 6);
#pragma unroll
                for (int r = 0; r < 3; r++) {
                    int z = ty + 32 * r;
                    int i = (z < p0) ? z : z + 32;
                    float av = Cs[i * CST + q];
                    ull a2 = pack2(av, av);
                    ffma2(acc2[r][0], a2, b0);
                    ffma2(acc2[r][1], a2, b1);
                    ffma2(acc2[r][2], a2, b2);
                    ffma2(acc2[r][3], a2, b3);
                }
            }
#pragma unroll
            for (int r = 0; r < 3; r++) {
                int z = ty + 32 * r;
                int i = (z < p0) ? z : z + 32;
#pragma unroll
                for (int c = 0; c < 4; c++) {
                    int l = tx * 8 + 2 * c;
                    float lo, hi;
                    unpack2(acc2[r][c], lo, hi);
                    float* Mp = M + i * MST + l;
                    bool inP0 = (l >= p0 && l < p0 + 32);
                    bool inP1 = (l + 1 >= p0 && l + 1 < p0 + 32);
                    float o0 = (inP0 ? 0.0f : Mp[0]) - lo;
                    float o1 = (inP1 ? 0.0f : Mp[1]) - hi;
                    Mp[0] = o0;
                    Mp[1] = o1;
                }
            }
            __syncthreads();
        }
    }

#pragma unroll
    for (int u = 0; u < 8; u++) {
        int v = tid + u * 512;
        int m = v >> 5, c4 = (v & 31) << 2;
        *(float4*)(Si + m * 128 + c4) = *(const float4*)(M + m * MST + c4);
    }
}

// ---------------------------------------------------------------------------
// solve_fused: all 3 Neumann passes in ONE CTA per (b,dir). 32 CTAs x 256 thr.
// smem: Sinv 64K | D 64K | X 64K. X holds R, then X0, then X1.
// X0 kept in registers for the base subtraction; T = D∘X computed on the fly.
// ---------------------------------------------------------------------------
#define SOLVE_SMEM (3 * 65536)

template<bool USED>
__device__ __forceinline__ void solve_pass(const float* __restrict__ Ss,
                                           const float* __restrict__ Ds,
                                           const float* __restrict__ Xs,
                                           int mbase, int nb, ull acc[8][4]) {
#pragma unroll
    for (int r = 0; r < 8; r++)
#pragma unroll
        for (int c = 0; c < 4; c++) acc[r][c] = 0ULL;
#pragma unroll 4
    for (int k = 0; k < 128; k++) {
        ull b0 = *(const ull*)&Ss[k * 128 + nb + 0];
        ull b1 = *(const ull*)&Ss[k * 128 + nb + 2];
        ull b2 = *(const ull*)&Ss[k * 128 + nb + 4];
        ull b3 = *(const ull*)&Ss[k * 128 + nb + 6];
#pragma unroll
        for (int r = 0; r < 8; r++) {
            float xv = Xs[(mbase + r) * 128 + k];
            float tv = USED ? Ds[(mbase + r) * 128 + k] * xv : xv;
            ull a2 = pack2(tv, tv);
            ffma2(acc[r][0], a2, b0);
            ffma2(acc[r][1], a2, b1);
            ffma2(acc[r][2], a2, b2);
            ffma2(acc[r][3], a2, b3);
        }
    }
}

__global__ void __launch_bounds__(256, 1) solve_fused(float* __restrict__ out) {
    extern __shared__ float ssm[];
    float* Ss = ssm;            // Sinv
    float* Ds = ssm + 16384;    // D
    float* Xs = ssm + 32768;    // R -> X0 -> X1
    int id = blockIdx.x;
    int b = id >> 1, dir = id & 1;
    const float* Sinv = g_Sinv + (size_t)id * KK * KK;
    const float* Dm = g_D + (size_t)id * KK * KK;
    const float* Rb = (dir ? g_RT : g_R) + (size_t)b * KK * KK;
    float* Cout = out + (size_t)(dir ? BB * KK * KK : 0) + (size_t)b * KK * KK;
    int tid = threadIdx.x;
    unsigned sS = smem_u32(Ss), sD = smem_u32(Ds), sX = smem_u32(Xs);

#pragma unroll
    for (int u = 0; u < 16; u++) {
        int v = tid + u * 256;
        unsigned off = (unsigned)v * 16;
        asm volatile("cp.async.cg.shared.global [%0], [%1], 16;"
                     :: "r"(sS + off), "l"((const float4*)Sinv + v) : "memory");
        asm volatile("cp.async.cg.shared.global [%0], [%1], 16;"
                     :: "r"(sD + off), "l"((const float4*)Dm + v) : "memory");
        asm volatile("cp.async.cg.shared.global [%0], [%1], 16;"
                     :: "r"(sX + off), "l"((const float4*)Rb + v) : "memory");
    }
    asm volatile("cp.async.commit_group;" ::: "memory");
    asm volatile("cp.async.wait_group 0;" ::: "memory");
    __syncthreads();

    int ty = tid >> 4, tx = tid & 15;
    int mbase = ty * 8, nb = tx * 8;

    ull acc0[8][4], acc[8][4];

    // pass 0: X0 = R * Sinv (Xs holds R)
    solve_pass<false>(Ss, Ds, Xs, mbase, nb, acc0);
    __syncthreads();          // all threads done reading R
#pragma unroll
    for (int r = 0; r < 8; r++)
#pragma unroll
        for (int c = 0; c < 4; c++)
            *(ull*)&Xs[(mbase + r) * 128 + nb + 2 * c] = acc0[r][c];
    __syncthreads();

    // pass 1: X1 = X0 - (D o X0) * Sinv
    solve_pass<true>(Ss, Ds, Xs, mbase, nb, acc);
    __syncthreads();          // all threads done reading X0
#pragma unroll
    for (int r = 0; r < 8; r++)
#pragma unroll
        for (int c = 0; c < 4; c++) {
            float l0, h0, l1, h1;
            unpack2(acc0[r][c], l0, h0);
            unpack2(acc[r][c], l1, h1);
            *(ull*)&Xs[(mbase + r) * 128 + nb + 2 * c] = pack2(l0 - l1, h0 - h1);
        }
    __syncthreads();

    // pass 2: out = X0 - (D o X1) * Sinv
    solve_pass<true>(Ss, Ds, Xs, mbase, nb, acc);
#pragma unroll
    for (int r = 0; r < 8; r++)
#pragma unroll
        for (int c = 0; c < 4; c++) {
            float l0, h0, l1, h1;
            unpack2(acc0[r][c], l0, h0);
            unpack2(acc[r][c], l1, h1);
            *(float2*)&Cout[(mbase + r) * 128 + nb + 2 * c] =
                make_float2(l0 - l1, h0 - h1);
        }
}

// ---------------------------------------------------------------------------
extern "C" void kernel_launch(void* const* d_in, const int* in_sizes, int n_in,
                              void* d_out, int out_size) {
    const float* feat_x  = (const float*)d_in[0];
    const float* feat_y  = (const float*)d_in[1];
    const float* evals_x = (const float*)d_in[2];
    const float* evals_y = (const float*)d_in[3];
    const float* evecs_x = (const float*)d_in[4];
    const float* evecs_y = (const float*)d_in[5];
    const float* aux_x   = (const float*)d_in[6];
    const float* aux_y   = (const float*)d_in[7];
    float* out = (float*)d_out;

    split_E<<<dim3(8192, 2), 256>>>(evecs_x, evecs_y);

    cudaFuncSetAttribute(mma_proj, cudaFuncAttributeMaxDynamicSharedMemorySize, MMA_SMEM);
    mma_proj<<<dim3(4, 32), 256, MMA_SMEM>>>(feat_x, feat_y);

    cudaFuncSetAttribute(gemm_nt_hmma, cudaFuncAttributeMaxDynamicSharedMemorySize, NT_SMEM);
    gemm_nt_hmma<<<48, 256, NT_SMEM>>>();

    cudaFuncSetAttribute(invert_mask, cudaFuncAttributeMaxDynamicSharedMemorySize, INV_SMEM);
    invert_mask<<<32, 512, INV_SMEM>>>(evals_x, evals_y, aux_x, aux_y);

    cudaFuncSetAttribute(solve_fused, cudaFuncAttributeMaxDynamicSharedMemorySize, SOLVE_SMEM);
    solve_fused<<<32, 256, SOLVE_SMEM>>>(out);
}